// round 7
// baseline (speedup 1.0000x reference)
#include <cuda_runtime.h>
#include <cuda_bf16.h>
#include <math.h>

#define NMAX 100000
#define EMAX 1600000
#define FDIM 128
#define FFDIM 512

// ---------------- scratch (static device globals; no allocation) ----------------
__device__ float g_xl [(size_t)NMAX * FDIM];  // source-side transform (gathered)
__device__ float g_xr [(size_t)NMAX * FDIM];  // target-side transform
__device__ float g_h  [(size_t)NMAX * FDIM];  // GAT output (+bias), residual stream
__device__ float g_t  [(size_t)NMAX * FDIM];  // LN1 output
__device__ float g_u  [(size_t)NMAX * FFDIM]; // silu(t@W1+b)
__device__ float g_wcat[FDIM * 256];          // [Wl | Wr] concatenated along cols
__device__ float g_bcat[256];

// CSR build scratch
__device__ int g_deg [NMAX];
__device__ int g_off [NMAX];
__device__ int g_cur [NMAX];
__device__ int g_inc [NMAX];
__device__ int g_bsum[1024];
__device__ int g_srcs[EMAX];

// ---------------- weight concat prep ----------------
__global__ void prep_wcat(const float* __restrict__ Wl, const float* __restrict__ Wr,
                          const float* __restrict__ bl, const float* __restrict__ br) {
    int i = blockIdx.x * blockDim.x + threadIdx.x;
    if (i < FDIM * 256) {
        int k = i >> 8, j = i & 255;
        g_wcat[i] = (j < 128) ? Wl[k * 128 + j] : Wr[k * 128 + (j - 128)];
    }
    if (i < 256) g_bcat[i] = (i < 128) ? bl[i] : br[i - 128];
}

// ---------------- CSR build ----------------
__global__ void k_hist(const int* __restrict__ ei, int E_) {
    int i = blockIdx.x * blockDim.x + threadIdx.x;
    if (i < E_) atomicAdd(&g_deg[ei[E_ + i]], 1);
}

__global__ void k_scan1(int n) {
    __shared__ int sm[256];
    int t = threadIdx.x;
    int idx = blockIdx.x * 256 + t;
    int v = (idx < n) ? g_deg[idx] : 0;
    sm[t] = v;
    __syncthreads();
#pragma unroll
    for (int o = 1; o < 256; o <<= 1) {
        int add = (t >= o) ? sm[t - o] : 0;
        __syncthreads();
        sm[t] += add;
        __syncthreads();
    }
    if (idx < n) g_inc[idx] = sm[t];
    if (t == 255) g_bsum[blockIdx.x] = sm[255];
}

__global__ void k_scan2(int nblocks) {
    __shared__ int sm[1024];
    int t = threadIdx.x;
    sm[t] = (t < nblocks) ? g_bsum[t] : 0;
    __syncthreads();
#pragma unroll
    for (int o = 1; o < 1024; o <<= 1) {
        int add = (t >= o) ? sm[t - o] : 0;
        __syncthreads();
        sm[t] += add;
        __syncthreads();
    }
    if (t < nblocks) g_bsum[t] = sm[t];
}

__global__ void k_scan3(int n) {
    int idx = blockIdx.x * blockDim.x + threadIdx.x;
    if (idx >= n) return;
    int b = idx >> 8;
    int prev = (b > 0) ? g_bsum[b - 1] : 0;
    int excl = g_inc[idx] - g_deg[idx] + prev;
    g_off[idx] = excl;
    g_cur[idx] = excl;
}

__global__ void k_scatter(const int* __restrict__ ei, int E_) {
    int i = blockIdx.x * blockDim.x + threadIdx.x;
    if (i >= E_) return;
    int dst = ei[E_ + i];
    int pos = atomicAdd(&g_cur[dst], 1);
    g_srcs[pos] = ei[i];
}

// ---------------- fused GAT gather + LayerNorm1 (R4-proven structure) ----------------
// one warp per node; lane covers 4 channels (float4); head = lane>>2
__global__ void __launch_bounds__(256)
k_gather_ln(const float* __restrict__ att, const float* __restrict__ bias,
            const float* __restrict__ g1, const float* __restrict__ bn1, int n) {
    int warp = (blockIdx.x * blockDim.x + threadIdx.x) >> 5;
    int lane = threadIdx.x & 31;
    if (warp >= n) return;

    const float4* xl4 = (const float4*)g_xl;
    float4 xr = ((const float4*)g_xr)[(size_t)warp * 32 + lane];
    float4 w  = ((const float4*)att)[lane];

    int start = g_off[warp];
    int deg   = g_deg[warp];

    float4 ws = make_float4(0.f, 0.f, 0.f, 0.f);
    float den = 0.f;

#define EDGE_STEP(a)                                                           \
    {                                                                          \
        float4 t;                                                              \
        t.x = a.x + xr.x; t.x = t.x > 0.f ? t.x : 0.2f * t.x;                  \
        t.y = a.y + xr.y; t.y = t.y > 0.f ? t.y : 0.2f * t.y;                  \
        t.z = a.z + xr.z; t.z = t.z > 0.f ? t.z : 0.2f * t.z;                  \
        t.w = a.w + xr.w; t.w = t.w > 0.f ? t.w : 0.2f * t.w;                  \
        float p = t.x * w.x + t.y * w.y + t.z * w.z + t.w * w.w;               \
        p += __shfl_xor_sync(0xffffffffu, p, 1);                               \
        p += __shfl_xor_sync(0xffffffffu, p, 2);                               \
        float ex = __expf(p);                                                  \
        den += ex;                                                             \
        ws.x += ex * a.x; ws.y += ex * a.y;                                    \
        ws.z += ex * a.z; ws.w += ex * a.w;                                    \
    }

    int j = 0;
    for (; j + 4 <= deg; j += 4) {
        int s0 = g_srcs[start + j + 0];
        int s1 = g_srcs[start + j + 1];
        int s2 = g_srcs[start + j + 2];
        int s3 = g_srcs[start + j + 3];
        float4 a0 = xl4[(size_t)s0 * 32 + lane];
        float4 a1 = xl4[(size_t)s1 * 32 + lane];
        float4 a2 = xl4[(size_t)s2 * 32 + lane];
        float4 a3 = xl4[(size_t)s3 * 32 + lane];
        EDGE_STEP(a0) EDGE_STEP(a1) EDGE_STEP(a2) EDGE_STEP(a3)
    }
    for (; j < deg; j++) {
        int s = g_srcs[start + j];
        float4 a = xl4[(size_t)s * 32 + lane];
        EDGE_STEP(a)
    }
#undef EDGE_STEP

    float invd = (den > 0.f) ? (1.f / den) : 0.f;
    float4 bb = ((const float4*)bias)[lane];
    float4 o;
    o.x = ws.x * invd + bb.x;
    o.y = ws.y * invd + bb.y;
    o.z = ws.z * invd + bb.z;
    o.w = ws.w * invd + bb.w;
    ((float4*)(g_h + (size_t)warp * 128))[lane] = o;

    // fused LayerNorm1 -> g_t
    float s  = o.x + o.y + o.z + o.w;
    float sq = o.x * o.x + o.y * o.y + o.z * o.z + o.w * o.w;
#pragma unroll
    for (int of = 16; of; of >>= 1) {
        s  += __shfl_xor_sync(0xffffffffu, s, of);
        sq += __shfl_xor_sync(0xffffffffu, sq, of);
    }
    float mu = s * (1.f / 128.f);
    float var = sq * (1.f / 128.f) - mu * mu;
    float rstd = rsqrtf(var + 1e-5f);
    float4 gg = ((const float4*)g1)[lane];
    float4 b1 = ((const float4*)bn1)[lane];
    float4 t4;
    t4.x = (o.x - mu) * rstd * gg.x + b1.x;
    t4.y = (o.y - mu) * rstd * gg.y + b1.y;
    t4.z = (o.z - mu) * rstd * gg.z + b1.z;
    t4.w = (o.w - mu) * rstd * gg.w + b1.w;
    ((float4*)(g_t + (size_t)warp * 128))[lane] = t4;
}

// ---------------- TF32 tensor-core GEMM ----------------
__device__ __forceinline__ unsigned f2tf32(float f) {
    unsigned r;
    asm("cvt.rna.tf32.f32 %0, %1;" : "=r"(r) : "f"(f));
    return r;
}

// C[M,N] = A[M,K] @ B[K,N] + bias, optional silu. BM=128, BN=128, BK=32.
// If C2 != null: blocks with bcol>=128 write C2 at (bcol-128), row stride ldc.
__global__ void __launch_bounds__(256, 2)
mma_gemm(const float* __restrict__ A, const float* __restrict__ Bm,
         float* __restrict__ C, float* __restrict__ C2,
         const float* __restrict__ bias,
         int M, int N, int K, int ldc, int act) {
    __shared__ unsigned As[128][36];
    __shared__ unsigned Bs[32][136];

    const int tid  = threadIdx.x;
    const int warp = tid >> 5;
    const int lane = tid & 31;
    const int wm   = (warp >> 1) * 32;
    const int wn   = (warp & 1) * 64;
    const int g    = lane >> 2;
    const int tg   = lane & 3;
    const int brow = blockIdx.y * 128;
    const int bcol = blockIdx.x * 128;

    float* Cb = C;
    int cb = bcol;
    if (C2 && bcol >= 128) { Cb = C2; cb = bcol - 128; }

    float acc[2][8][4];
#pragma unroll
    for (int i = 0; i < 2; i++)
#pragma unroll
        for (int j = 0; j < 8; j++)
#pragma unroll
            for (int q = 0; q < 4; q++) acc[i][j][q] = 0.f;

    const int arow   = tid >> 3;
    const int acol   = (tid & 7) * 4;
    const int brow_l = tid >> 5;
    const int bcol_l = (tid & 31) * 4;

    for (int k0 = 0; k0 < K; k0 += 32) {
#pragma unroll
        for (int i = 0; i < 4; i++) {
            int r = arow + i * 32;
            int grow = brow + r;
            float4 v = (grow < M) ? *(const float4*)(A + (size_t)grow * K + k0 + acol)
                                  : make_float4(0.f, 0.f, 0.f, 0.f);
            As[r][acol + 0] = f2tf32(v.x);
            As[r][acol + 1] = f2tf32(v.y);
            As[r][acol + 2] = f2tf32(v.z);
            As[r][acol + 3] = f2tf32(v.w);
        }
#pragma unroll
        for (int i = 0; i < 4; i++) {
            int r = brow_l + i * 8;
            float4 v = *(const float4*)(Bm + (size_t)(k0 + r) * N + bcol + bcol_l);
            Bs[r][bcol_l + 0] = f2tf32(v.x);
            Bs[r][bcol_l + 1] = f2tf32(v.y);
            Bs[r][bcol_l + 2] = f2tf32(v.z);
            Bs[r][bcol_l + 3] = f2tf32(v.w);
        }
        __syncthreads();

#pragma unroll
        for (int ks = 0; ks < 4; ks++) {
            const int kk = ks * 8;
            unsigned a[2][4], b[8][2];
#pragma unroll
            for (int mt = 0; mt < 2; mt++) {
                int rm = wm + mt * 16 + g;
                a[mt][0] = As[rm][kk + tg];
                a[mt][1] = As[rm + 8][kk + tg];
                a[mt][2] = As[rm][kk + tg + 4];
                a[mt][3] = As[rm + 8][kk + tg + 4];
            }
#pragma unroll
            for (int nt = 0; nt < 8; nt++) {
                int cn = wn + nt * 8 + g;
                b[nt][0] = Bs[kk + tg][cn];
                b[nt][1] = Bs[kk + tg + 4][cn];
            }
#pragma unroll
            for (int mt = 0; mt < 2; mt++)
#pragma unroll
                for (int nt = 0; nt < 8; nt++) {
                    asm volatile(
                        "mma.sync.aligned.m16n8k8.row.col.f32.tf32.tf32.f32 "
                        "{%0,%1,%2,%3}, {%4,%5,%6,%7}, {%8,%9}, {%0,%1,%2,%3};\n"
                        : "+f"(acc[mt][nt][0]), "+f"(acc[mt][nt][1]),
                          "+f"(acc[mt][nt][2]), "+f"(acc[mt][nt][3])
                        : "r"(a[mt][0]), "r"(a[mt][1]), "r"(a[mt][2]), "r"(a[mt][3]),
                          "r"(b[nt][0]), "r"(b[nt][1]));
                }
        }
        __syncthreads();
    }

#pragma unroll
    for (int mt = 0; mt < 2; mt++) {
        int r0 = brow + wm + mt * 16 + g;
        int r1 = r0 + 8;
#pragma unroll
        for (int nt = 0; nt < 8; nt++) {
            int cfull = bcol + wn + nt * 8 + 2 * tg;
            int c = cb + wn + nt * 8 + 2 * tg;
            float b0 = bias[cfull], b1 = bias[cfull + 1];
            float v00 = acc[mt][nt][0] + b0;
            float v01 = acc[mt][nt][1] + b1;
            float v10 = acc[mt][nt][2] + b0;
            float v11 = acc[mt][nt][3] + b1;
            if (act) {
                v00 = v00 / (1.f + __expf(-v00));
                v01 = v01 / (1.f + __expf(-v01));
                v10 = v10 / (1.f + __expf(-v10));
                v11 = v11 / (1.f + __expf(-v11));
            }
            if (r0 < M) *(float2*)(Cb + (size_t)r0 * ldc + c) = make_float2(v00, v01);
            if (r1 < M) *(float2*)(Cb + (size_t)r1 * ldc + c) = make_float2(v10, v11);
        }
    }
}

// ---------------- final GEMM (u @ W2 + bW2) fused with residual + LayerNorm2 ----------------
__global__ void __launch_bounds__(256, 2)
mma_gemm_ln(const float* __restrict__ A, const float* __restrict__ Bm,
            const float* __restrict__ h, float* __restrict__ Out,
            const float* __restrict__ bias,
            const float* __restrict__ g2, const float* __restrict__ bn2,
            int M, int K) {
    const int N = 128;
    __shared__ unsigned As[128][36];
    __shared__ unsigned Bs[32][136];
    __shared__ float ssum[128][2];
    __shared__ float ssq [128][2];

    const int tid  = threadIdx.x;
    const int warp = tid >> 5;
    const int lane = tid & 31;
    const int wm   = (warp >> 1) * 32;
    const int wn   = (warp & 1) * 64;
    const int g    = lane >> 2;
    const int tg   = lane & 3;
    const int brow = blockIdx.y * 128;

    float acc[2][8][4];
#pragma unroll
    for (int i = 0; i < 2; i++)
#pragma unroll
        for (int j = 0; j < 8; j++)
#pragma unroll
            for (int q = 0; q < 4; q++) acc[i][j][q] = 0.f;

    const int arow   = tid >> 3;
    const int acol   = (tid & 7) * 4;
    const int brow_l = tid >> 5;
    const int bcol_l = (tid & 31) * 4;

    for (int k0 = 0; k0 < K; k0 += 32) {
#pragma unroll
        for (int i = 0; i < 4; i++) {
            int r = arow + i * 32;
            int grow = brow + r;
            float4 v = (grow < M) ? *(const float4*)(A + (size_t)grow * K + k0 + acol)
                                  : make_float4(0.f, 0.f, 0.f, 0.f);
            As[r][acol + 0] = f2tf32(v.x);
            As[r][acol + 1] = f2tf32(v.y);
            As[r][acol + 2] = f2tf32(v.z);
            As[r][acol + 3] = f2tf32(v.w);
        }
#pragma unroll
        for (int i = 0; i < 4; i++) {
            int r = brow_l + i * 8;
            float4 v = *(const float4*)(Bm + (size_t)(k0 + r) * N + bcol_l);
            Bs[r][bcol_l + 0] = f2tf32(v.x);
            Bs[r][bcol_l + 1] = f2tf32(v.y);
            Bs[r][bcol_l + 2] = f2tf32(v.z);
            Bs[r][bcol_l + 3] = f2tf32(v.w);
        }
        __syncthreads();

#pragma unroll
        for (int ks = 0; ks < 4; ks++) {
            const int kk = ks * 8;
            unsigned a[2][4], b[8][2];
#pragma unroll
            for (int mt = 0; mt < 2; mt++) {
                int rm = wm + mt * 16 + g;
                a[mt][0] = As[rm][kk + tg];
                a[mt][1] = As[rm + 8][kk + tg];
                a[mt][2] = As[rm][kk + tg + 4];
                a[mt][3] = As[rm + 8][kk + tg + 4];
            }
#pragma unroll
            for (int nt = 0; nt < 8; nt++) {
                int cn = wn + nt * 8 + g;
                b[nt][0] = Bs[kk + tg][cn];
                b[nt][1] = Bs[kk + tg + 4][cn];
            }
#pragma unroll
            for (int mt = 0; mt < 2; mt++)
#pragma unroll
                for (int nt = 0; nt < 8; nt++) {
                    asm volatile(
                        "mma.sync.aligned.m16n8k8.row.col.f32.tf32.tf32.f32 "
                        "{%0,%1,%2,%3}, {%4,%5,%6,%7}, {%8,%9}, {%0,%1,%2,%3};\n"
                        : "+f"(acc[mt][nt][0]), "+f"(acc[mt][nt][1]),
                          "+f"(acc[mt][nt][2]), "+f"(acc[mt][nt][3])
                        : "r"(a[mt][0]), "r"(a[mt][1]), "r"(a[mt][2]), "r"(a[mt][3]),
                          "r"(b[nt][0]), "r"(b[nt][1]));
                }
        }
        __syncthreads();
    }

    // ---- epilogue: vals = acc + bias + h; per-row LN ----
    float rs[2][2] = {{0.f, 0.f}, {0.f, 0.f}};
    float rq[2][2] = {{0.f, 0.f}, {0.f, 0.f}};
#pragma unroll
    for (int mt = 0; mt < 2; mt++) {
        int r0 = brow + wm + mt * 16 + g;
        int r1 = r0 + 8;
#pragma unroll
        for (int nt = 0; nt < 8; nt++) {
            int c = wn + nt * 8 + 2 * tg;
            float b0 = bias[c], b1 = bias[c + 1];
            float v00 = acc[mt][nt][0] + b0;
            float v01 = acc[mt][nt][1] + b1;
            float v10 = acc[mt][nt][2] + b0;
            float v11 = acc[mt][nt][3] + b1;
            if (r0 < M) {
                float2 hh = *(const float2*)(h + (size_t)r0 * 128 + c);
                v00 += hh.x; v01 += hh.y;
            }
            if (r1 < M) {
                float2 hh = *(const float2*)(h + (size_t)r1 * 128 + c);
                v10 += hh.x; v11 += hh.y;
            }
            acc[mt][nt][0] = v00; acc[mt][nt][1] = v01;
            acc[mt][nt][2] = v10; acc[mt][nt][3] = v11;
            rs[mt][0] += v00 + v01;
            rq[mt][0] += v00 * v00 + v01 * v01;
            rs[mt][1] += v10 + v11;
            rq[mt][1] += v10 * v10 + v11 * v11;
        }
    }
#pragma unroll
    for (int mt = 0; mt < 2; mt++)
#pragma unroll
        for (int hf = 0; hf < 2; hf++) {
            rs[mt][hf] += __shfl_xor_sync(0xffffffffu, rs[mt][hf], 1);
            rs[mt][hf] += __shfl_xor_sync(0xffffffffu, rs[mt][hf], 2);
            rq[mt][hf] += __shfl_xor_sync(0xffffffffu, rq[mt][hf], 1);
            rq[mt][hf] += __shfl_xor_sync(0xffffffffu, rq[mt][hf], 2);
        }
    if (tg == 0) {
#pragma unroll
        for (int mt = 0; mt < 2; mt++)
#pragma unroll
            for (int hf = 0; hf < 2; hf++) {
                int rl = wm + mt * 16 + hf * 8 + g;
                ssum[rl][wn >> 6] = rs[mt][hf];
                ssq [rl][wn >> 6] = rq[mt][hf];
            }
    }
    __syncthreads();

#pragma unroll
    for (int mt = 0; mt < 2; mt++) {
#pragma unroll
        for (int hf = 0; hf < 2; hf++) {
            int rl = wm + mt * 16 + hf * 8 + g;
            int rg = brow + rl;
            if (rg >= M) continue;
            float s  = ssum[rl][0] + ssum[rl][1];
            float sq = ssq [rl][0] + ssq [rl][1];
            float mu = s * (1.f / 128.f);
            float var = sq * (1.f / 128.f) - mu * mu;
            float rstd = rsqrtf(var + 1e-5f);
#pragma unroll
            for (int nt = 0; nt < 8; nt++) {
                int c = wn + nt * 8 + 2 * tg;
                float va = acc[mt][nt][hf * 2 + 0];
                float vb = acc[mt][nt][hf * 2 + 1];
                float o0 = (va - mu) * rstd * g2[c]     + bn2[c];
                float o1 = (vb - mu) * rstd * g2[c + 1] + bn2[c + 1];
                *(float2*)(Out + (size_t)rg * 128 + c) = make_float2(o0, o1);
            }
        }
    }
}

// ---------------- launch ----------------
extern "C" void kernel_launch(void* const* d_in, const int* in_sizes, int n_in,
                              void* d_out, int out_size) {
    const float* x        = (const float*)d_in[0];
    const int*   ei       = (const int*)  d_in[1];
    const float* Wl       = (const float*)d_in[2];
    const float* bl       = (const float*)d_in[3];
    const float* Wr       = (const float*)d_in[4];
    const float* br       = (const float*)d_in[5];
    const float* att      = (const float*)d_in[6];
    const float* bias_gat = (const float*)d_in[7];
    const float* g1       = (const float*)d_in[8];
    const float* bn1      = (const float*)d_in[9];
    const float* W1       = (const float*)d_in[10];
    const float* bW1      = (const float*)d_in[11];
    const float* W2       = (const float*)d_in[12];
    const float* bW2      = (const float*)d_in[13];
    const float* g2       = (const float*)d_in[14];
    const float* bn2      = (const float*)d_in[15];
    float* out = (float*)d_out;

    const int n = in_sizes[0] / FDIM;      // 100000
    const int E = in_sizes[1] / 2;         // 1600000

    float *p_xl, *p_xr, *p_t, *p_u, *p_h, *p_wcat, *p_bcat;
    int *p_deg;
    cudaGetSymbolAddress((void**)&p_xl,   g_xl);
    cudaGetSymbolAddress((void**)&p_xr,   g_xr);
    cudaGetSymbolAddress((void**)&p_t,    g_t);
    cudaGetSymbolAddress((void**)&p_u,    g_u);
    cudaGetSymbolAddress((void**)&p_h,    g_h);
    cudaGetSymbolAddress((void**)&p_wcat, g_wcat);
    cudaGetSymbolAddress((void**)&p_bcat, g_bcat);
    cudaGetSymbolAddress((void**)&p_deg,  g_deg);

    const int scan_blocks = (n + 255) / 256;

    prep_wcat<<<(FDIM * 256 + 255) / 256, 256>>>(Wl, Wr, bl, br);
    cudaMemsetAsync(p_deg, 0, (size_t)n * sizeof(int), 0);

    k_hist<<<(E + 255) / 256, 256>>>(ei, E);
    k_scan1<<<scan_blocks, 256>>>(n);
    k_scan2<<<1, 1024>>>(scan_blocks);
    k_scan3<<<scan_blocks, 256>>>(n);
    k_scatter<<<(E + 255) / 256, 256>>>(ei, E);

    const int MB = (n + 127) / 128;

    // 1) [xl|xr] = x @ [Wl|Wr] + [bl|br]  (tf32, split outputs)
    mma_gemm<<<dim3(2, MB), 256>>>(x, p_wcat, p_xl, p_xr, p_bcat, n, 256, 128, 128, 0);

    // 2) fused GAT gather + LN1
    k_gather_ln<<<(n + 7) / 8, 256>>>(att, bias_gat, g1, bn1, n);

    // 3) u = silu(t @ W1 + bW1)  (tf32)
    mma_gemm<<<dim3(4, MB), 256>>>(p_t, W1, p_u, nullptr, bW1, n, 512, 128, 512, 1);

    // 4) out = LN2(h + u @ W2 + bW2)  (tf32, fused residual + LN)
    mma_gemm_ln<<<dim3(1, MB), 256>>>(p_u, W2, p_h, out, bW2, g2, bn2, n, 512);
}

// round 8
// speedup vs baseline: 1.4034x; 1.4034x over previous
#include <cuda_runtime.h>
#include <cuda_bf16.h>
#include <math.h>

#define NMAX 100000
#define EMAX 1600000
#define FDIM 128
#define FFDIM 512

// ---------------- scratch (static device globals; no allocation) ----------------
__device__ float s_xl [(size_t)NMAX * FDIM];  // source-side transform (gathered)
__device__ float s_xr [(size_t)NMAX * FDIM];  // target-side transform
__device__ float s_h  [(size_t)NMAX * FDIM];  // GAT output (+bias), residual stream
__device__ float s_t  [(size_t)NMAX * FDIM];  // LN1 output
__device__ float s_u  [(size_t)NMAX * FFDIM]; // silu(t@W1+b)
__device__ float s_wcat[FDIM * 256];          // [Wl | Wr] concatenated along cols
__device__ float s_bcat[256];

// CSR build scratch
__device__ int s_deg [NMAX];
__device__ int s_off [NMAX];
__device__ int s_cur [NMAX];
__device__ int s_inc [NMAX];
__device__ int s_bsum[1024];
__device__ int s_srcs[EMAX];

// ---------------- weight concat prep ----------------
__global__ void kz_prep(const float* __restrict__ Wl, const float* __restrict__ Wr,
                        const float* __restrict__ bl, const float* __restrict__ br) {
    int i = blockIdx.x * blockDim.x + threadIdx.x;
    if (i < FDIM * 256) {
        int k = i >> 8, j = i & 255;
        s_wcat[i] = (j < 128) ? Wl[k * 128 + j] : Wr[k * 128 + (j - 128)];
    }
    if (i < 256) s_bcat[i] = (i < 128) ? bl[i] : br[i - 128];
}

// ---------------- CSR build ----------------
__global__ void kz_hist(const int* __restrict__ ei, int E_) {
    int i = blockIdx.x * blockDim.x + threadIdx.x;
    if (i < E_) atomicAdd(&s_deg[ei[E_ + i]], 1);
}

__global__ void kz_scan1(int n) {
    __shared__ int sm[256];
    int t = threadIdx.x;
    int idx = blockIdx.x * 256 + t;
    int v = (idx < n) ? s_deg[idx] : 0;
    sm[t] = v;
    __syncthreads();
#pragma unroll
    for (int o = 1; o < 256; o <<= 1) {
        int add = (t >= o) ? sm[t - o] : 0;
        __syncthreads();
        sm[t] += add;
        __syncthreads();
    }
    if (idx < n) s_inc[idx] = sm[t];
    if (t == 255) s_bsum[blockIdx.x] = sm[255];
}

__global__ void kz_scan2(int nblocks) {
    __shared__ int sm[1024];
    int t = threadIdx.x;
    sm[t] = (t < nblocks) ? s_bsum[t] : 0;
    __syncthreads();
#pragma unroll
    for (int o = 1; o < 1024; o <<= 1) {
        int add = (t >= o) ? sm[t - o] : 0;
        __syncthreads();
        sm[t] += add;
        __syncthreads();
    }
    if (t < nblocks) s_bsum[t] = sm[t];
}

__global__ void kz_scan3(int n) {
    int idx = blockIdx.x * blockDim.x + threadIdx.x;
    if (idx >= n) return;
    int b = idx >> 8;
    int prev = (b > 0) ? s_bsum[b - 1] : 0;
    int excl = s_inc[idx] - s_deg[idx] + prev;
    s_off[idx] = excl;
    s_cur[idx] = excl;
}

__global__ void kz_scatter(const int* __restrict__ ei, int E_) {
    int i = blockIdx.x * blockDim.x + threadIdx.x;
    if (i >= E_) return;
    int dst = ei[E_ + i];
    int pos = atomicAdd(&s_cur[dst], 1);
    s_srcs[pos] = ei[i];
}

// ---------------- fused GAT gather + LayerNorm1 (R4-proven structure) ----------------
__global__ void __launch_bounds__(256)
kz_gather_ln(const float* __restrict__ att, const float* __restrict__ bias,
             const float* __restrict__ g1, const float* __restrict__ bn1, int n) {
    int warp = (blockIdx.x * blockDim.x + threadIdx.x) >> 5;
    int lane = threadIdx.x & 31;
    if (warp >= n) return;

    const float4* xl4 = (const float4*)s_xl;
    float4 xr = ((const float4*)s_xr)[(size_t)warp * 32 + lane];
    float4 w  = ((const float4*)att)[lane];

    int start = s_off[warp];
    int deg   = s_deg[warp];

    float4 ws = make_float4(0.f, 0.f, 0.f, 0.f);
    float den = 0.f;

#define EDGE_STEP(a)                                                           \
    {                                                                          \
        float4 t;                                                              \
        t.x = a.x + xr.x; t.x = t.x > 0.f ? t.x : 0.2f * t.x;                  \
        t.y = a.y + xr.y; t.y = t.y > 0.f ? t.y : 0.2f * t.y;                  \
        t.z = a.z + xr.z; t.z = t.z > 0.f ? t.z : 0.2f * t.z;                  \
        t.w = a.w + xr.w; t.w = t.w > 0.f ? t.w : 0.2f * t.w;                  \
        float p = t.x * w.x + t.y * w.y + t.z * w.z + t.w * w.w;               \
        p += __shfl_xor_sync(0xffffffffu, p, 1);                               \
        p += __shfl_xor_sync(0xffffffffu, p, 2);                               \
        float ex = __expf(p);                                                  \
        den += ex;                                                             \
        ws.x += ex * a.x; ws.y += ex * a.y;                                    \
        ws.z += ex * a.z; ws.w += ex * a.w;                                    \
    }

    int j = 0;
    for (; j + 4 <= deg; j += 4) {
        int q0 = s_srcs[start + j + 0];
        int q1 = s_srcs[start + j + 1];
        int q2 = s_srcs[start + j + 2];
        int q3 = s_srcs[start + j + 3];
        float4 a0 = xl4[(size_t)q0 * 32 + lane];
        float4 a1 = xl4[(size_t)q1 * 32 + lane];
        float4 a2 = xl4[(size_t)q2 * 32 + lane];
        float4 a3 = xl4[(size_t)q3 * 32 + lane];
        EDGE_STEP(a0) EDGE_STEP(a1) EDGE_STEP(a2) EDGE_STEP(a3)
    }
    for (; j < deg; j++) {
        int q = s_srcs[start + j];
        float4 a = xl4[(size_t)q * 32 + lane];
        EDGE_STEP(a)
    }
#undef EDGE_STEP

    float invd = (den > 0.f) ? (1.f / den) : 0.f;
    float4 bb = ((const float4*)bias)[lane];
    float4 o;
    o.x = ws.x * invd + bb.x;
    o.y = ws.y * invd + bb.y;
    o.z = ws.z * invd + bb.z;
    o.w = ws.w * invd + bb.w;
    ((float4*)(s_h + (size_t)warp * 128))[lane] = o;

    // fused LayerNorm1 -> s_t
    float sm  = o.x + o.y + o.z + o.w;
    float sq = o.x * o.x + o.y * o.y + o.z * o.z + o.w * o.w;
#pragma unroll
    for (int of = 16; of; of >>= 1) {
        sm += __shfl_xor_sync(0xffffffffu, sm, of);
        sq += __shfl_xor_sync(0xffffffffu, sq, of);
    }
    float mu = sm * (1.f / 128.f);
    float var = sq * (1.f / 128.f) - mu * mu;
    float rstd = rsqrtf(var + 1e-5f);
    float4 gg = ((const float4*)g1)[lane];
    float4 b1 = ((const float4*)bn1)[lane];
    float4 t4;
    t4.x = (o.x - mu) * rstd * gg.x + b1.x;
    t4.y = (o.y - mu) * rstd * gg.y + b1.y;
    t4.z = (o.z - mu) * rstd * gg.z + b1.z;
    t4.w = (o.w - mu) * rstd * gg.w + b1.w;
    ((float4*)(s_t + (size_t)warp * 128))[lane] = t4;
}

// ---------------- TF32 tensor-core GEMM ----------------
__device__ __forceinline__ unsigned to_tf32(float f) {
    unsigned r;
    asm("cvt.rna.tf32.f32 %0, %1;" : "=r"(r) : "f"(f));
    return r;
}

__global__ void __launch_bounds__(256, 2)
kz_mma(const float* __restrict__ A, const float* __restrict__ Bm,
       float* __restrict__ C, float* __restrict__ C2,
       const float* __restrict__ bias,
       int M, int N, int K, int ldc, int act) {
    __shared__ unsigned As[128][36];
    __shared__ unsigned Bs[32][136];

    const int tid  = threadIdx.x;
    const int warp = tid >> 5;
    const int lane = tid & 31;
    const int wm   = (warp >> 1) * 32;
    const int wn   = (warp & 1) * 64;
    const int g    = lane >> 2;
    const int tg   = lane & 3;
    const int brow = blockIdx.y * 128;
    const int bcol = blockIdx.x * 128;

    float* Cb = C;
    int cb = bcol;
    if (C2 && bcol >= 128) { Cb = C2; cb = bcol - 128; }

    float acc[2][8][4];
#pragma unroll
    for (int i = 0; i < 2; i++)
#pragma unroll
        for (int j = 0; j < 8; j++)
#pragma unroll
            for (int q = 0; q < 4; q++) acc[i][j][q] = 0.f;

    const int arow   = tid >> 3;
    const int acol   = (tid & 7) * 4;
    const int brow_l = tid >> 5;
    const int bcol_l = (tid & 31) * 4;

    for (int k0 = 0; k0 < K; k0 += 32) {
#pragma unroll
        for (int i = 0; i < 4; i++) {
            int r = arow + i * 32;
            int grow = brow + r;
            float4 v = (grow < M) ? *(const float4*)(A + (size_t)grow * K + k0 + acol)
                                  : make_float4(0.f, 0.f, 0.f, 0.f);
            As[r][acol + 0] = to_tf32(v.x);
            As[r][acol + 1] = to_tf32(v.y);
            As[r][acol + 2] = to_tf32(v.z);
            As[r][acol + 3] = to_tf32(v.w);
        }
#pragma unroll
        for (int i = 0; i < 4; i++) {
            int r = brow_l + i * 8;
            float4 v = *(const float4*)(Bm + (size_t)(k0 + r) * N + bcol + bcol_l);
            Bs[r][bcol_l + 0] = to_tf32(v.x);
            Bs[r][bcol_l + 1] = to_tf32(v.y);
            Bs[r][bcol_l + 2] = to_tf32(v.z);
            Bs[r][bcol_l + 3] = to_tf32(v.w);
        }
        __syncthreads();

#pragma unroll
        for (int ks = 0; ks < 4; ks++) {
            const int kk = ks * 8;
            unsigned a[2][4], b[8][2];
#pragma unroll
            for (int mt = 0; mt < 2; mt++) {
                int rm = wm + mt * 16 + g;
                a[mt][0] = As[rm][kk + tg];
                a[mt][1] = As[rm + 8][kk + tg];
                a[mt][2] = As[rm][kk + tg + 4];
                a[mt][3] = As[rm + 8][kk + tg + 4];
            }
#pragma unroll
            for (int nt = 0; nt < 8; nt++) {
                int cn = wn + nt * 8 + g;
                b[nt][0] = Bs[kk + tg][cn];
                b[nt][1] = Bs[kk + tg + 4][cn];
            }
#pragma unroll
            for (int mt = 0; mt < 2; mt++)
#pragma unroll
                for (int nt = 0; nt < 8; nt++) {
                    asm volatile(
                        "mma.sync.aligned.m16n8k8.row.col.f32.tf32.tf32.f32 "
                        "{%0,%1,%2,%3}, {%4,%5,%6,%7}, {%8,%9}, {%0,%1,%2,%3};\n"
                        : "+f"(acc[mt][nt][0]), "+f"(acc[mt][nt][1]),
                          "+f"(acc[mt][nt][2]), "+f"(acc[mt][nt][3])
                        : "r"(a[mt][0]), "r"(a[mt][1]), "r"(a[mt][2]), "r"(a[mt][3]),
                          "r"(b[nt][0]), "r"(b[nt][1]));
                }
        }
        __syncthreads();
    }

#pragma unroll
    for (int mt = 0; mt < 2; mt++) {
        int r0 = brow + wm + mt * 16 + g;
        int r1 = r0 + 8;
#pragma unroll
        for (int nt = 0; nt < 8; nt++) {
            int cfull = bcol + wn + nt * 8 + 2 * tg;
            int c = cb + wn + nt * 8 + 2 * tg;
            float b0 = bias[cfull], b1 = bias[cfull + 1];
            float v00 = acc[mt][nt][0] + b0;
            float v01 = acc[mt][nt][1] + b1;
            float v10 = acc[mt][nt][2] + b0;
            float v11 = acc[mt][nt][3] + b1;
            if (act) {
                v00 = v00 / (1.f + __expf(-v00));
                v01 = v01 / (1.f + __expf(-v01));
                v10 = v10 / (1.f + __expf(-v10));
                v11 = v11 / (1.f + __expf(-v11));
            }
            if (r0 < M) *(float2*)(Cb + (size_t)r0 * ldc + c) = make_float2(v00, v01);
            if (r1 < M) *(float2*)(Cb + (size_t)r1 * ldc + c) = make_float2(v10, v11);
        }
    }
}

// ---------------- final GEMM (u @ W2 + bW2) fused with residual + LayerNorm2 ----------------
__global__ void __launch_bounds__(256, 2)
kz_mma_ln(const float* __restrict__ A, const float* __restrict__ Bm,
          const float* __restrict__ h, float* __restrict__ Out,
          const float* __restrict__ bias,
          const float* __restrict__ g2, const float* __restrict__ bn2,
          int M, int K) {
    const int N = 128;
    __shared__ unsigned As[128][36];
    __shared__ unsigned Bs[32][136];
    __shared__ float ssum[128][2];
    __shared__ float ssq [128][2];

    const int tid  = threadIdx.x;
    const int warp = tid >> 5;
    const int lane = tid & 31;
    const int wm   = (warp >> 1) * 32;
    const int wn   = (warp & 1) * 64;
    const int g    = lane >> 2;
    const int tg   = lane & 3;
    const int brow = blockIdx.y * 128;

    float acc[2][8][4];
#pragma unroll
    for (int i = 0; i < 2; i++)
#pragma unroll
        for (int j = 0; j < 8; j++)
#pragma unroll
            for (int q = 0; q < 4; q++) acc[i][j][q] = 0.f;

    const int arow   = tid >> 3;
    const int acol   = (tid & 7) * 4;
    const int brow_l = tid >> 5;
    const int bcol_l = (tid & 31) * 4;

    for (int k0 = 0; k0 < K; k0 += 32) {
#pragma unroll
        for (int i = 0; i < 4; i++) {
            int r = arow + i * 32;
            int grow = brow + r;
            float4 v = (grow < M) ? *(const float4*)(A + (size_t)grow * K + k0 + acol)
                                  : make_float4(0.f, 0.f, 0.f, 0.f);
            As[r][acol + 0] = to_tf32(v.x);
            As[r][acol + 1] = to_tf32(v.y);
            As[r][acol + 2] = to_tf32(v.z);
            As[r][acol + 3] = to_tf32(v.w);
        }
#pragma unroll
        for (int i = 0; i < 4; i++) {
            int r = brow_l + i * 8;
            float4 v = *(const float4*)(Bm + (size_t)(k0 + r) * N + bcol_l);
            Bs[r][bcol_l + 0] = to_tf32(v.x);
            Bs[r][bcol_l + 1] = to_tf32(v.y);
            Bs[r][bcol_l + 2] = to_tf32(v.z);
            Bs[r][bcol_l + 3] = to_tf32(v.w);
        }
        __syncthreads();

#pragma unroll
        for (int ks = 0; ks < 4; ks++) {
            const int kk = ks * 8;
            unsigned a[2][4], b[8][2];
#pragma unroll
            for (int mt = 0; mt < 2; mt++) {
                int rm = wm + mt * 16 + g;
                a[mt][0] = As[rm][kk + tg];
                a[mt][1] = As[rm + 8][kk + tg];
                a[mt][2] = As[rm][kk + tg + 4];
                a[mt][3] = As[rm + 8][kk + tg + 4];
            }
#pragma unroll
            for (int nt = 0; nt < 8; nt++) {
                int cn = wn + nt * 8 + g;
                b[nt][0] = Bs[kk + tg][cn];
                b[nt][1] = Bs[kk + tg + 4][cn];
            }
#pragma unroll
            for (int mt = 0; mt < 2; mt++)
#pragma unroll
                for (int nt = 0; nt < 8; nt++) {
                    asm volatile(
                        "mma.sync.aligned.m16n8k8.row.col.f32.tf32.tf32.f32 "
                        "{%0,%1,%2,%3}, {%4,%5,%6,%7}, {%8,%9}, {%0,%1,%2,%3};\n"
                        : "+f"(acc[mt][nt][0]), "+f"(acc[mt][nt][1]),
                          "+f"(acc[mt][nt][2]), "+f"(acc[mt][nt][3])
                        : "r"(a[mt][0]), "r"(a[mt][1]), "r"(a[mt][2]), "r"(a[mt][3]),
                          "r"(b[nt][0]), "r"(b[nt][1]));
                }
        }
        __syncthreads();
    }

    // ---- epilogue: vals = acc + bias + h; per-row LN ----
    float rs[2][2] = {{0.f, 0.f}, {0.f, 0.f}};
    float rq[2][2] = {{0.f, 0.f}, {0.f, 0.f}};
#pragma unroll
    for (int mt = 0; mt < 2; mt++) {
        int r0 = brow + wm + mt * 16 + g;
        int r1 = r0 + 8;
#pragma unroll
        for (int nt = 0; nt < 8; nt++) {
            int c = wn + nt * 8 + 2 * tg;
            float b0 = bias[c], b1 = bias[c + 1];
            float v00 = acc[mt][nt][0] + b0;
            float v01 = acc[mt][nt][1] + b1;
            float v10 = acc[mt][nt][2] + b0;
            float v11 = acc[mt][nt][3] + b1;
            if (r0 < M) {
                float2 hh = *(const float2*)(h + (size_t)r0 * 128 + c);
                v00 += hh.x; v01 += hh.y;
            }
            if (r1 < M) {
                float2 hh = *(const float2*)(h + (size_t)r1 * 128 + c);
                v10 += hh.x; v11 += hh.y;
            }
            acc[mt][nt][0] = v00; acc[mt][nt][1] = v01;
            acc[mt][nt][2] = v10; acc[mt][nt][3] = v11;
            rs[mt][0] += v00 + v01;
            rq[mt][0] += v00 * v00 + v01 * v01;
            rs[mt][1] += v10 + v11;
            rq[mt][1] += v10 * v10 + v11 * v11;
        }
    }
#pragma unroll
    for (int mt = 0; mt < 2; mt++)
#pragma unroll
        for (int hf = 0; hf < 2; hf++) {
            rs[mt][hf] += __shfl_xor_sync(0xffffffffu, rs[mt][hf], 1);
            rs[mt][hf] += __shfl_xor_sync(0xffffffffu, rs[mt][hf], 2);
            rq[mt][hf] += __shfl_xor_sync(0xffffffffu, rq[mt][hf], 1);
            rq[mt][hf] += __shfl_xor_sync(0xffffffffu, rq[mt][hf], 2);
        }
    if (tg == 0) {
#pragma unroll
        for (int mt = 0; mt < 2; mt++)
#pragma unroll
            for (int hf = 0; hf < 2; hf++) {
                int rl = wm + mt * 16 + hf * 8 + g;
                ssum[rl][wn >> 6] = rs[mt][hf];
                ssq [rl][wn >> 6] = rq[mt][hf];
            }
    }
    __syncthreads();

#pragma unroll
    for (int mt = 0; mt < 2; mt++) {
#pragma unroll
        for (int hf = 0; hf < 2; hf++) {
            int rl = wm + mt * 16 + hf * 8 + g;
            int rg = brow + rl;
            if (rg >= M) continue;
            float sm  = ssum[rl][0] + ssum[rl][1];
            float sq = ssq [rl][0] + ssq [rl][1];
            float mu = sm * (1.f / 128.f);
            float var = sq * (1.f / 128.f) - mu * mu;
            float rstd = rsqrtf(var + 1e-5f);
#pragma unroll
            for (int nt = 0; nt < 8; nt++) {
                int c = wn + nt * 8 + 2 * tg;
                float va = acc[mt][nt][hf * 2 + 0];
                float vb = acc[mt][nt][hf * 2 + 1];
                float o0 = (va - mu) * rstd * g2[c]     + bn2[c];
                float o1 = (vb - mu) * rstd * g2[c + 1] + bn2[c + 1];
                *(float2*)(Out + (size_t)rg * 128 + c) = make_float2(o0, o1);
            }
        }
    }
}

// ---------------- launch ----------------
extern "C" void kernel_launch(void* const* d_in, const int* in_sizes, int n_in,
                              void* d_out, int out_size) {
    const float* x        = (const float*)d_in[0];
    const int*   ei       = (const int*)  d_in[1];
    const float* Wl       = (const float*)d_in[2];
    const float* bl       = (const float*)d_in[3];
    const float* Wr       = (const float*)d_in[4];
    const float* br       = (const float*)d_in[5];
    const float* att      = (const float*)d_in[6];
    const float* bias_gat = (const float*)d_in[7];
    const float* g1       = (const float*)d_in[8];
    const float* bn1      = (const float*)d_in[9];
    const float* W1       = (const float*)d_in[10];
    const float* bW1      = (const float*)d_in[11];
    const float* W2       = (const float*)d_in[12];
    const float* bW2      = (const float*)d_in[13];
    const float* g2       = (const float*)d_in[14];
    const float* bn2      = (const float*)d_in[15];
    float* out = (float*)d_out;

    const int n = in_sizes[0] / FDIM;      // 100000
    const int E = in_sizes[1] / 2;         // 1600000

    float *p_xl, *p_xr, *p_t, *p_u, *p_h, *p_wcat, *p_bcat;
    int *p_deg;
    cudaGetSymbolAddress((void**)&p_xl,   s_xl);
    cudaGetSymbolAddress((void**)&p_xr,   s_xr);
    cudaGetSymbolAddress((void**)&p_t,    s_t);
    cudaGetSymbolAddress((void**)&p_u,    s_u);
    cudaGetSymbolAddress((void**)&p_h,    s_h);
    cudaGetSymbolAddress((void**)&p_wcat, s_wcat);
    cudaGetSymbolAddress((void**)&p_bcat, s_bcat);
    cudaGetSymbolAddress((void**)&p_deg,  s_deg);

    const int scan_blocks = (n + 255) / 256;

    kz_prep<<<(FDIM * 256 + 255) / 256, 256>>>(Wl, Wr, bl, br);
    cudaMemsetAsync(p_deg, 0, (size_t)n * sizeof(int), 0);

    kz_hist<<<(E + 255) / 256, 256>>>(ei, E);
    kz_scan1<<<scan_blocks, 256>>>(n);
    kz_scan2<<<1, 1024>>>(scan_blocks);
    kz_scan3<<<scan_blocks, 256>>>(n);
    kz_scatter<<<(E + 255) / 256, 256>>>(ei, E);

    const int MB = (n + 127) / 128;

    // 1) [xl|xr] = x @ [Wl|Wr] + [bl|br]  (tf32, split outputs)
    kz_mma<<<dim3(2, MB), 256>>>(x, p_wcat, p_xl, p_xr, p_bcat, n, 256, 128, 128, 0);

    // 2) fused GAT gather + LN1
    kz_gather_ln<<<(n + 7) / 8, 256>>>(att, bias_gat, g1, bn1, n);

    // 3) u = silu(t @ W1 + bW1)  (tf32)
    kz_mma<<<dim3(4, MB), 256>>>(p_t, W1, p_u, nullptr, bW1, n, 512, 128, 512, 1);

    // 4) out = LN2(h + u @ W2 + bW2)  (tf32, fused residual + LN)
    kz_mma_ln<<<dim3(1, MB), 256>>>(p_u, W2, p_h, out, bW2, g2, bn2, n, 512);
}